// round 3
// baseline (speedup 1.0000x reference)
#include <cuda_runtime.h>
#include <cuda_bf16.h>

// Problem constants (fixed by setup_inputs):
//   encoder_output: (B=32, L_ENC=512, E=256) float32
//   durations:      (B=32, L_ENC=512) int32, values in [0, 8)
//   output:         (B=32, L_DEC=2048, E=256) float32
//
// Semantics: out[b, d, :] = enc[b, l, :] where l is the unique encoder
// position with excl_cumsum[l] <= d < incl_cumsum[l]; zero if d >= total_b.

#define B_SZ    32
#define L_ENC   512
#define L_DEC   2048
#define E_DIM   256
#define E_VEC   (E_DIM / 4)   // 64 float4 per row

// Scratch for per-batch inclusive cumsum of durations.
__device__ int g_cumsum[B_SZ * L_ENC];

// ---------------------------------------------------------------------------
// Kernel 1: inclusive scan of durations per batch. One block per batch.
// ---------------------------------------------------------------------------
__global__ void lr_cumsum_kernel(const int* __restrict__ dur)
{
    __shared__ int s[L_ENC];
    const int b = blockIdx.x;
    const int t = threadIdx.x;

    s[t] = dur[b * L_ENC + t];
    __syncthreads();

    // Hillis-Steele inclusive scan over 512 elements.
    #pragma unroll
    for (int off = 1; off < L_ENC; off <<= 1) {
        int v = (t >= off) ? s[t - off] : 0;
        __syncthreads();
        s[t] += v;
        __syncthreads();
    }

    g_cumsum[b * L_ENC + t] = s[t];
}

// ---------------------------------------------------------------------------
// Kernel 2: for each (b, d) decoder row, find the source encoder row via a
// branchless upper-bound on the staged cumsum, then copy 256 floats
// (64 x float4). Zero if past end.
// Block: 256 threads = 4 row-groups of 64 lanes. Grid: (L_DEC/4, B).
// ---------------------------------------------------------------------------
__global__ void lr_gather_kernel(const float4* __restrict__ enc,
                                 float4* __restrict__ out)
{
    __shared__ int scs[L_ENC];
    const int b = blockIdx.y;
    const int t = threadIdx.x;             // 0..255

    // Stage this batch's cumsum into shared (2 ints per thread).
    scs[t]       = g_cumsum[b * L_ENC + t];
    scs[t + 256] = g_cumsum[b * L_ENC + t + 256];
    __syncthreads();

    const int group = t >> 6;              // 0..3: which decoder row
    const int lane  = t & 63;              // 0..63: which float4 in row
    const int d     = blockIdx.x * 4 + group;

    // upper_bound: pos = first l with scs[l] > d, pos in [0, 512].
    // Branchless power-of-two counting search; all smem reads in-bounds
    // (index pos+step-1 <= 511 whenever pos+step <= 512).
    // All 64 lanes of a group share d -> uniform path, broadcast smem reads.
    int pos = 0;
    #pragma unroll
    for (int step = L_ENC; step > 0; step >>= 1) {
        int nxt = pos + step;
        if (nxt <= L_ENC && scs[nxt - 1] <= d) pos = nxt;
    }

    const long out_idx = ((long)(b * L_DEC + d)) * E_VEC + lane;
    if (pos < L_ENC) {
        const long enc_idx = ((long)(b * L_ENC + pos)) * E_VEC + lane;
        out[out_idx] = enc[enc_idx];
    } else {
        out[out_idx] = make_float4(0.f, 0.f, 0.f, 0.f);
    }
}

// ---------------------------------------------------------------------------
extern "C" void kernel_launch(void* const* d_in, const int* in_sizes, int n_in,
                              void* d_out, int out_size)
{
    const float* enc = (const float*)d_in[0];     // (B, L_ENC, E)
    const int*   dur = (const int*)d_in[1];       // (B, L_ENC) int32
    (void)in_sizes; (void)n_in; (void)out_size;

    lr_cumsum_kernel<<<B_SZ, L_ENC>>>(dur);
    dim3 grid(L_DEC / 4, B_SZ);
    lr_gather_kernel<<<grid, 256>>>((const float4*)enc, (float4*)d_out);
}

// round 4
// speedup vs baseline: 1.1433x; 1.1433x over previous
#include <cuda_runtime.h>
#include <cuda_bf16.h>

// Problem constants (fixed by setup_inputs):
//   encoder_output: (B=32, L_ENC=512, E=256) float32
//   durations:      (B=32, L_ENC=512) int32, values in [0, 8)
//   output:         (B=32, L_DEC=2048, E=256) float32
//
// out[b, d, :] = enc[b, l, :] where excl_cs[l] <= d < incl_cs[l]; 0 past end.

#define B_SZ    32
#define L_ENC   512
#define L_DEC   2048
#define E_DIM   256
#define E_VEC   (E_DIM / 4)            // 64 float4 per row
#define DEC_PER_THREAD (L_DEC / L_ENC) // 4

// Per-decoder-position source row (absolute: b*L_ENC + l), or -1 for padding.
__device__ int g_src[B_SZ * L_DEC];

// ---------------------------------------------------------------------------
// Kernel A: per-batch scan of durations + direct scatter of source indices.
// One block per batch, 512 threads.
// ---------------------------------------------------------------------------
__global__ void lr_index_kernel(const int* __restrict__ dur)
{
    __shared__ int s[L_ENC];
    const int b = blockIdx.x;
    const int t = threadIdx.x;

    const int my_dur = dur[b * L_ENC + t];
    s[t] = my_dur;
    __syncthreads();

    // Hillis-Steele inclusive scan over 512 elements.
    #pragma unroll
    for (int off = 1; off < L_ENC; off <<= 1) {
        int v = (t >= off) ? s[t - off] : 0;
        __syncthreads();
        s[t] += v;
        __syncthreads();
    }

    const int incl = s[t];
    const int excl = incl - my_dur;

    int* src_b = g_src + b * L_DEC;

    // Pre-fill with -1 (padding sentinel).
    #pragma unroll
    for (int i = 0; i < DEC_PER_THREAD; ++i)
        src_b[t * DEC_PER_THREAD + i] = -1;
    __syncthreads();

    // Scatter: decoder positions [excl, min(incl, L_DEC)) map to encoder row t.
    const int hi = incl < L_DEC ? incl : L_DEC;
    const int row = b * L_ENC + t;
    for (int d = excl; d < hi; ++d)
        src_b[d] = row;
}

// ---------------------------------------------------------------------------
// Kernel B: pure gather-copy. One thread per output float4.
// 64 consecutive threads share one decoder row (broadcast index load).
// ---------------------------------------------------------------------------
__global__ void lr_copy_kernel(const float4* __restrict__ enc,
                               float4* __restrict__ out)
{
    const int idx  = blockIdx.x * blockDim.x + threadIdx.x;  // float4 index
    const int drow = idx >> 6;            // global decoder row (b*L_DEC + d)
    const int lane = idx & 63;

    const int src = g_src[drow];
    float4 v = make_float4(0.f, 0.f, 0.f, 0.f);
    if (src >= 0)
        v = enc[(long)src * E_VEC + lane];
    out[idx] = v;
}

// ---------------------------------------------------------------------------
extern "C" void kernel_launch(void* const* d_in, const int* in_sizes, int n_in,
                              void* d_out, int out_size)
{
    const float* enc = (const float*)d_in[0];     // (B, L_ENC, E)
    const int*   dur = (const int*)d_in[1];       // (B, L_ENC) int32
    (void)in_sizes; (void)n_in; (void)out_size;

    lr_index_kernel<<<B_SZ, L_ENC>>>(dur);

    const int total_vec = B_SZ * L_DEC * E_VEC;   // 4,194,304 float4
    lr_copy_kernel<<<total_vec / 256, 256>>>((const float4*)enc,
                                             (float4*)d_out);
}

// round 5
// speedup vs baseline: 1.2676x; 1.1087x over previous
#include <cuda_runtime.h>
#include <cuda_bf16.h>

// Problem constants (fixed by setup_inputs):
//   encoder_output: (B=32, L_ENC=512, E=256) float32
//   durations:      (B=32, L_ENC=512) int32, values in [0, 8)
//   output:         (B=32, L_DEC=2048, E=256) float32
//
// out[b, d, :] = enc[b, l, :] where excl_cs[l] <= d < incl_cs[l]; 0 past end.

#define B_SZ    32
#define L_ENC   512
#define L_DEC   2048
#define E_DIM   256
#define E_VEC   (E_DIM / 4)            // 64 float4 per row
#define DEC_PER_THREAD (L_DEC / L_ENC) // 4
#define TOTAL_VEC (B_SZ * L_DEC * E_VEC)   // 4,194,304 float4
#define UNROLL  4
#define STRIDE  (TOTAL_VEC / UNROLL)       // 1,048,576

// Per-decoder-position source row (absolute: b*L_ENC + l), or -1 for padding.
__device__ int g_src[B_SZ * L_DEC];

// ---------------------------------------------------------------------------
// Kernel A: per-batch scan of durations + direct scatter of source indices.
// One block per batch, 512 threads.
// ---------------------------------------------------------------------------
__global__ void lr_index_kernel(const int* __restrict__ dur)
{
    __shared__ int s[L_ENC];
    const int b = blockIdx.x;
    const int t = threadIdx.x;

    const int my_dur = dur[b * L_ENC + t];
    s[t] = my_dur;
    __syncthreads();

    // Hillis-Steele inclusive scan over 512 elements.
    #pragma unroll
    for (int off = 1; off < L_ENC; off <<= 1) {
        int v = (t >= off) ? s[t - off] : 0;
        __syncthreads();
        s[t] += v;
        __syncthreads();
    }

    const int incl = s[t];
    const int excl = incl - my_dur;

    int* src_b = g_src + b * L_DEC;

    // Pre-fill with -1 (padding sentinel).
    #pragma unroll
    for (int i = 0; i < DEC_PER_THREAD; ++i)
        src_b[t * DEC_PER_THREAD + i] = -1;
    __syncthreads();

    // Scatter: decoder positions [excl, min(incl, L_DEC)) map to encoder row t.
    const int hi = incl < L_DEC ? incl : L_DEC;
    const int row = b * L_ENC + t;
    for (int d = excl; d < hi; ++d)
        src_b[d] = row;
}

// ---------------------------------------------------------------------------
// Kernel B: gather-copy with 4 independent chains per thread (MLP=4).
// Thread handles float4 positions base + j*STRIDE, j=0..3. Within each
// region, 64 consecutive threads cover one decoder row (coalesced 128b
// loads/stores; index load broadcasts across the 64-thread group).
// ---------------------------------------------------------------------------
__global__ void lr_copy_kernel(const float4* __restrict__ enc,
                               float4* __restrict__ out)
{
    const int base = blockIdx.x * blockDim.x + threadIdx.x;

    // Phase 1: batch all index loads.
    int src[UNROLL];
    #pragma unroll
    for (int j = 0; j < UNROLL; ++j) {
        const int idx = base + j * STRIDE;
        src[j] = g_src[idx >> 6];
    }

    // Phase 2: batch all data loads (unconditional via clamp, select after).
    float4 v[UNROLL];
    #pragma unroll
    for (int j = 0; j < UNROLL; ++j) {
        const int lane = (base + j * STRIDE) & 63;
        const int safe = src[j] >= 0 ? src[j] : 0;
        v[j] = enc[(long)safe * E_VEC + lane];
    }

    // Phase 3: select zeros for padding rows, store.
    #pragma unroll
    for (int j = 0; j < UNROLL; ++j) {
        if (src[j] < 0) v[j] = make_float4(0.f, 0.f, 0.f, 0.f);
        out[base + j * STRIDE] = v[j];
    }
}

// ---------------------------------------------------------------------------
extern "C" void kernel_launch(void* const* d_in, const int* in_sizes, int n_in,
                              void* d_out, int out_size)
{
    const float* enc = (const float*)d_in[0];     // (B, L_ENC, E)
    const int*   dur = (const int*)d_in[1];       // (B, L_ENC) int32
    (void)in_sizes; (void)n_in; (void)out_size;

    lr_index_kernel<<<B_SZ, L_ENC>>>(dur);

    lr_copy_kernel<<<STRIDE / 512, 512>>>((const float4*)enc,
                                          (float4*)d_out);
}

// round 6
// speedup vs baseline: 1.4383x; 1.1347x over previous
#include <cuda_runtime.h>
#include <cuda_bf16.h>

// Problem constants (fixed by setup_inputs):
//   encoder_output: (B=32, L_ENC=512, E=256) float32
//   durations:      (B=32, L_ENC=512) int32, values in [0, 8)
//   output:         (B=32, L_DEC=2048, E=256) float32
//
// out[b, d, :] = enc[b, l, :] where excl_cs[l] <= d < incl_cs[l]; 0 past end.

#define B_SZ    32
#define L_ENC   512
#define L_DEC   2048
#define E_DIM   256
#define E_VEC   (E_DIM / 4)            // 64 float4 per row
#define DEC_PER_THREAD (L_DEC / L_ENC) // 4
#define TOTAL_VEC (B_SZ * L_DEC * E_VEC)   // 4,194,304 float4
#define UNROLL  8
#define STRIDE  (TOTAL_VEC / UNROLL)       // 524,288

// Per-decoder-position source row (absolute: b*L_ENC + l), or -1 for padding.
__device__ int g_src[B_SZ * L_DEC];

// ---------------------------------------------------------------------------
// Kernel A: per-batch scan of durations (warp-shuffle based) + scatter of
// source indices. One block per batch, 512 threads (16 warps).
// ---------------------------------------------------------------------------
__global__ void lr_index_kernel(const int* __restrict__ dur)
{
    __shared__ int warp_sums[16];
    const int b    = blockIdx.x;
    const int t    = threadIdx.x;
    const int wid  = t >> 5;
    const int lane = t & 31;

    const int my_dur = dur[b * L_ENC + t];

    // Inclusive warp scan.
    int v = my_dur;
    #pragma unroll
    for (int off = 1; off < 32; off <<= 1) {
        int u = __shfl_up_sync(0xffffffffu, v, off);
        if (lane >= off) v += u;
    }
    if (lane == 31) warp_sums[wid] = v;
    __syncthreads();

    // Warp 0 scans the 16 warp sums (exclusive result back to smem).
    if (wid == 0 && lane < 16) {
        int ws = warp_sums[lane];
        #pragma unroll
        for (int off = 1; off < 16; off <<= 1) {
            int u = __shfl_up_sync(0x0000ffffu, ws, off);
            if (lane >= off) ws += u;
        }
        warp_sums[lane] = ws - warp_sums[lane];   // exclusive prefix
    }
    __syncthreads();

    const int incl = v + warp_sums[wid];
    const int excl = incl - my_dur;

    int* src_b = g_src + b * L_DEC;

    // Pre-fill with -1 (padding sentinel).
    #pragma unroll
    for (int i = 0; i < DEC_PER_THREAD; ++i)
        src_b[t * DEC_PER_THREAD + i] = -1;
    __syncthreads();

    // Scatter: decoder positions [excl, min(incl, L_DEC)) map to encoder row t.
    const int hi = incl < L_DEC ? incl : L_DEC;
    const int row = b * L_ENC + t;
    for (int d = excl; d < hi; ++d)
        src_b[d] = row;
}

// ---------------------------------------------------------------------------
// Kernel B: gather-copy with 8 independent chains per thread (MLP=8).
// Thread handles float4 positions base + j*STRIDE. Within each region,
// 64 consecutive threads cover one decoder row (coalesced 128b ld/st;
// index load broadcasts across the 64-thread group).
// ---------------------------------------------------------------------------
__global__ void lr_copy_kernel(const float4* __restrict__ enc,
                               float4* __restrict__ out)
{
    const int base = blockIdx.x * blockDim.x + threadIdx.x;

    // Phase 1: batch all index loads.
    int src[UNROLL];
    #pragma unroll
    for (int j = 0; j < UNROLL; ++j)
        src[j] = g_src[(base + j * STRIDE) >> 6];

    // Phase 2: batch all data loads (unconditional via clamp, select after).
    float4 v[UNROLL];
    #pragma unroll
    for (int j = 0; j < UNROLL; ++j) {
        const int lane = (base + j * STRIDE) & 63;
        const int safe = src[j] >= 0 ? src[j] : 0;
        v[j] = enc[(long)safe * E_VEC + lane];
    }

    // Phase 3: select zeros for padding rows, store.
    #pragma unroll
    for (int j = 0; j < UNROLL; ++j) {
        if (src[j] < 0) v[j] = make_float4(0.f, 0.f, 0.f, 0.f);
        out[base + j * STRIDE] = v[j];
    }
}

// ---------------------------------------------------------------------------
extern "C" void kernel_launch(void* const* d_in, const int* in_sizes, int n_in,
                              void* d_out, int out_size)
{
    const float* enc = (const float*)d_in[0];     // (B, L_ENC, E)
    const int*   dur = (const int*)d_in[1];       // (B, L_ENC) int32
    (void)in_sizes; (void)n_in; (void)out_size;

    lr_index_kernel<<<B_SZ, L_ENC>>>(dur);

    lr_copy_kernel<<<STRIDE / 512, 512>>>((const float4*)enc,
                                          (float4*)d_out);
}